// round 16
// baseline (speedup 1.0000x reference)
#include <cuda_runtime.h>
#include <cuda_fp16.h>
#include <math.h>

// Problem constants (fixed shapes per reference: N=100000, E=3200000, F_in=54, H=16, F_out=16)
#define MAXN 100000
#define MAXE 3200000
#define F_IN 54
#define F_H  16

#define SCAN_TILE 1024
#define MAX_TILES ((MAXN + SCAN_TILE - 1) / SCAN_TILE)   // 98

// ---------------- scratch (device globals; no allocation allowed) ----------------
__device__ int g_is64;                 // 1 if edge_index buffer is int64, 0 if int32
__device__ int g_deg[MAXN];
__device__ int g_rowptr[MAXN + 1];
__device__ int g_col[MAXE];
__device__ int g_dst32[MAXE];
__device__ unsigned short g_rank[MAXE];        // edge's arrival rank within its dst bucket
__device__ volatile int g_agg[MAX_TILES];      // tile aggregates (single-pass scan)
__device__ volatile int g_flag1[MAX_TILES];    // aggregate published
__device__ volatile int g_flag2[MAX_TILES];    // rowptr tile written
__device__ __align__(32) __half g_hh1[MAXN * F_H];  // layer-1 features (fp16)
__device__ __align__(32) __half g_hh2[MAXN * F_H];  // layer-2 features (fp16)
__device__ float g_ad1[MAXN];
__device__ float g_ad2[MAXN];

__device__ __forceinline__ int edge_at(const void* __restrict__ ei, size_t idx) {
    if (g_is64) return (int)((const long long*)ei)[idx];
    return ((const int*)ei)[idx];
}

// ---------------- launch 1: zero deg/flags + dtype sniff + node1 (blockIdx-partitioned) ----------------
// blocks [0, nbz): zero; blocks [nbz, nbz+nb1): h1 = x @ W1 (fp16), a1_dst dot.
__global__ __launch_bounds__(128) void k_init_node1(const int* __restrict__ ei_raw,
                                                    const float* __restrict__ x,
                                                    const float* __restrict__ W,
                                                    const float* __restrict__ adst,
                                                    int n, int nbz) {
    __shared__ float sw[F_IN * F_H];
    __shared__ float sx[128 * F_IN];
    int tid = threadIdx.x;

    if ((int)blockIdx.x < nbz) {
        int i = blockIdx.x * 128 + tid;
        if (i < n) g_deg[i] = 0;
        if (i < MAX_TILES) { g_flag1[i] = 0; g_flag2[i] = 0; }
        if (i == 0) {
            int all_hi_zero = 1;
            for (int j = 0; j < 32; j++) {
                if (ei_raw[2 * j + 1] != 0) { all_hi_zero = 0; break; }
            }
            g_is64 = all_hi_zero;
        }
        return;
    }

    // ---- node1 role ----
    for (int i = tid; i < F_IN * F_H; i += 128) sw[i] = W[i];
    int base = ((int)blockIdx.x - nbz) * 128;
    int cnt = min(128, n - base);
    if (cnt <= 0) return;
    for (int i = tid; i < cnt * F_IN; i += 128) sx[i] = x[(size_t)base * F_IN + i];
    __syncthreads();
    if (tid >= cnt) return;
    int node = base + tid;
    float acc[F_H];
#pragma unroll
    for (int k = 0; k < F_H; k++) acc[k] = 0.f;
    for (int j = 0; j < F_IN; j++) {
        float xv = sx[tid * F_IN + j];
#pragma unroll
        for (int k = 0; k < F_H; k++) acc[k] = fmaf(xv, sw[j * F_H + k], acc[k]);
    }
    float dd = 0.f;
#pragma unroll
    for (int k = 0; k < F_H; k++) dd = fmaf(acc[k], __ldg(&adst[k]), dd);
    g_ad1[node] = dd;
    unsigned u[8];
#pragma unroll
    for (int k = 0; k < 8; k++) {
        __half2 p = __floats2half2_rn(acc[2 * k], acc[2 * k + 1]);
        u[k] = *(unsigned*)&p;
    }
    uint4* hp = (uint4*)&g_hh1[(size_t)node * F_H];
    hp[0] = make_uint4(u[0], u[1], u[2], u[3]);
    hp[1] = make_uint4(u[4], u[5], u[6], u[7]);
}

// ---------------- launch 2: histogram + per-edge rank + dst int32 conversion ----------------
__global__ void k_hist(const void* __restrict__ ei, int e, int n) {
    int i = blockIdx.x * blockDim.x + threadIdx.x;
    if (i < e) {
        int d = edge_at(ei, (size_t)e + i);
        g_dst32[i] = d;
        if ((unsigned)d < (unsigned)n) {
            int r = atomicAdd(&g_deg[d], 1);
            g_rank[i] = (unsigned short)r;
        }
    }
}

// ---------------- launch 3: single-pass scan (flag-based) + scatter, one kernel ----------------
// blocks [0, ntiles): scan role. blocks [ntiles, ...): scatter role (spin on flag2).
// Safe: blocks 0..97 are in scheduling wave 1 (first 148 block ids), so scan always progresses.
__global__ __launch_bounds__(256) void k_scan_scatter(const void* __restrict__ ei,
                                                      int e, int n, int ntiles) {
    int t = threadIdx.x;
    if ((int)blockIdx.x < ntiles) {
        __shared__ int sh[256];
        __shared__ int ts[128];
        int b = blockIdx.x;
        int base = b * SCAN_TILE + t * 4;
        int v0 = 0, v1 = 0, v2 = 0, v3 = 0;
        if (base + 3 < n) {
            int4 v = *(const int4*)&g_deg[base];
            v0 = v.x; v1 = v.y; v2 = v.z; v3 = v.w;
        } else {
            if (base + 0 < n) v0 = g_deg[base + 0];
            if (base + 1 < n) v1 = g_deg[base + 1];
            if (base + 2 < n) v2 = g_deg[base + 2];
            if (base + 3 < n) v3 = g_deg[base + 3];
        }
        int local = v0 + v1 + v2 + v3;
        sh[t] = local;
        __syncthreads();
        for (int off = 1; off < 256; off <<= 1) {
            int x = sh[t];
            int a = (t >= off) ? sh[t - off] : 0;
            __syncthreads();
            sh[t] = x + a;
            __syncthreads();
        }
        // publish tile aggregate
        if (t == 0) {
            g_agg[b] = sh[255];
            __threadfence();
            g_flag1[b] = 1;
        }
        // collect ALL tile aggregates (parallel spin)
        if (t < 128) ts[t] = 0;
        if (t < ntiles) {
            while (g_flag1[t] == 0) __nanosleep(64);
        }
        __threadfence();
        if (t < ntiles) ts[t] = g_agg[t];
        __syncthreads();
        for (int off = 1; off < 128; off <<= 1) {
            int x = (t < 128) ? ts[t] : 0;
            int a = (t >= off && t < 128) ? ts[t - off] : 0;
            __syncthreads();
            if (t < 128) ts[t] = x + a;
            __syncthreads();
        }
        int blockoff = (b == 0) ? 0 : ts[b - 1];
        if (b == 0 && t == 0) g_rowptr[n] = ts[ntiles - 1];
        int run = blockoff + sh[t] - local;   // exclusive prefix for elem base+0
        int r0 = run, r1 = run + v0, r2 = r1 + v1, r3 = r2 + v2;
        if (base + 3 < n) {
            *(int4*)&g_rowptr[base] = make_int4(r0, r1, r2, r3);
        } else {
            if (base + 0 < n) g_rowptr[base + 0] = r0;
            if (base + 1 < n) g_rowptr[base + 1] = r1;
            if (base + 2 < n) g_rowptr[base + 2] = r2;
            if (base + 3 < n) g_rowptr[base + 3] = r3;
        }
        __threadfence();
        __syncthreads();
        if (t == 0) g_flag2[b] = 1;
    } else {
        // ---- scatter role: wait for full rowptr, then atomic-free scatter via ranks ----
        if (t < ntiles) {
            while (g_flag2[t] == 0) __nanosleep(64);
        }
        __syncthreads();
        __threadfence();
        int sb = (int)blockIdx.x - ntiles;
        int base = sb * 1024;
#pragma unroll
        for (int j = 0; j < 4; j++) {
            int i = base + j * 256 + t;
            if (i < e) {
                int s = edge_at(ei, (size_t)i);
                int d = g_dst32[i];
                if ((unsigned)d < (unsigned)n && (unsigned)s < (unsigned)n) {
                    int pos = g_rowptr[d] + (int)g_rank[i];
                    g_col[pos] = s;
                }
            }
        }
    }
}

__device__ __forceinline__ float leaky(float v) { return v > 0.f ? v : 0.2f * v; }

// unpack 2 uint4 (16 half) into f[16]
__device__ __forceinline__ void unp_row(const uint4& A, const uint4& B, float* f) {
    float2 t2;
#define UNP2(word, k0) { __half2 _h = *(__half2*)&(word); t2 = __half22float2(_h); f[k0] = t2.x; f[k0+1] = t2.y; }
    UNP2(A.x, 0)  UNP2(A.y, 2)  UNP2(A.z, 4)  UNP2(A.w, 6)
    UNP2(B.x, 8)  UNP2(B.y, 10) UNP2(B.z, 12) UNP2(B.w, 14)
#undef UNP2
}

// ---------------- launches 4/5: edge aggregation (R14 winner form) ----------------
// 8-lane group per dst node, single-pass softmax, src attention dot in registers.
// LAYER1: aggregates h1, bias+ELU, fused layer-2 transform -> g_hh2 / g_ad2.
// LAYER2: aggregates h2, adds b2, writes final output.
#define GRP 8
template <int LAYER1>
__global__ __launch_bounds__(256) void k_edge(const float* __restrict__ bias,
                                              const float* __restrict__ asrc,
                                              const float* __restrict__ W2,
                                              const float* __restrict__ a2d,
                                              float* __restrict__ outp,
                                              int n) {
    __shared__ float sw2[F_H * F_H];
    __shared__ float sa[F_H], sd2[F_H], sb[F_H];
    int tid = threadIdx.x;
    if (LAYER1) {
        for (int i = tid; i < F_H * F_H; i += 256) sw2[i] = W2[i];
    }
    if (tid < F_H) {
        sb[tid] = bias[tid];
        sa[tid] = asrc[tid];
        if (LAYER1) sd2[tid] = a2d[tid];
    }
    __syncthreads();

    int gid = (blockIdx.x * blockDim.x + tid) / GRP;   // node
    int sub = tid & (GRP - 1);
    if (gid >= n) return;

    const __half* __restrict__ hh = LAYER1 ? g_hh1 : g_hh2;
    float adv = LAYER1 ? g_ad1[gid] : g_ad2[gid];
    int beg = g_rowptr[gid];
    int end = g_rowptr[gid + 1];

    float acc[F_H];
#pragma unroll
    for (int k = 0; k < F_H; k++) acc[k] = 0.f;
    float den = 0.f;

    for (int i = beg + sub; i < end; i += GRP) {
        int s = g_col[i];
        const uint4* hp = (const uint4*)(hh + (size_t)s * F_H);
        uint4 A = __ldg(hp), B = __ldg(hp + 1);
        float f[F_H];
        unp_row(A, B, f);
        float as = 0.f;
#pragma unroll
        for (int k = 0; k < F_H; k++) as = fmaf(f[k], sa[k], as);
        float wt = __expf(leaky(as + adv));
        den += wt;
#pragma unroll
        for (int k = 0; k < F_H; k++) acc[k] = fmaf(wt, f[k], acc[k]);
    }

    // 8-lane butterfly: afterwards ALL lanes hold the full sums
#pragma unroll
    for (int o = GRP / 2; o; o >>= 1) {
        den += __shfl_xor_sync(0xffffffffu, den, o, GRP);
#pragma unroll
        for (int k = 0; k < F_H; k++)
            acc[k] += __shfl_xor_sync(0xffffffffu, acc[k], o, GRP);
    }

    // self-loop (lane-uniform within group)
    float hs[F_H];
    {
        const uint4* hp = (const uint4*)(hh + (size_t)gid * F_H);
        uint4 A = __ldg(hp), B = __ldg(hp + 1);
        unp_row(A, B, hs);
    }
    float as_self = 0.f;
#pragma unroll
    for (int k = 0; k < F_H; k++) as_self = fmaf(hs[k], sa[k], as_self);
    float ws = __expf(leaky(as_self + adv));
    den += ws;
    float inv = 1.0f / den;

    if (LAYER1) {
        float g1v[F_H];
#pragma unroll
        for (int k = 0; k < F_H; k++) {
            float v = (acc[k] + ws * hs[k]) * inv + sb[k];
            g1v[k] = v > 0.f ? v : expm1f(v);
        }
        int k0 = 2 * sub, k1 = 2 * sub + 1;
        float o0 = 0.f, o1 = 0.f;
#pragma unroll
        for (int j = 0; j < F_H; j++) {
            o0 = fmaf(g1v[j], sw2[j * F_H + k0], o0);
            o1 = fmaf(g1v[j], sw2[j * F_H + k1], o1);
        }
        float pd = o0 * sd2[k0] + o1 * sd2[k1];
#pragma unroll
        for (int o = GRP / 2; o; o >>= 1)
            pd += __shfl_xor_sync(0xffffffffu, pd, o, GRP);
        __half2 p = __floats2half2_rn(o0, o1);
        ((unsigned*)g_hh2)[(size_t)gid * 8 + sub] = *(unsigned*)&p;
        if (sub == 0) g_ad2[gid] = pd;
    } else {
        int k0 = 2 * sub;
        float v0 = (acc[k0] + ws * hs[k0]) * inv + sb[k0];
        float v1 = (acc[k0 + 1] + ws * hs[k0 + 1]) * inv + sb[k0 + 1];
        ((float2*)outp)[(size_t)gid * 8 + sub] = make_float2(v0, v1);
    }
}

// ---------------- launch ----------------
extern "C" void kernel_launch(void* const* d_in, const int* in_sizes, int n_in,
                              void* d_out, int out_size) {
    const float* x   = (const float*)d_in[0];
    const void*  ei  = d_in[1];                    // int32 or int64 — sniffed on device
    const float* W1  = (const float*)d_in[2];
    const float* a1s = (const float*)d_in[3];
    const float* a1d = (const float*)d_in[4];
    const float* b1  = (const float*)d_in[5];
    const float* W2  = (const float*)d_in[6];
    const float* a2s = (const float*)d_in[7];
    const float* a2d = (const float*)d_in[8];
    const float* b2  = (const float*)d_in[9];
    float* out = (float*)d_out;

    int n = in_sizes[0] / F_IN;     // 100000
    int e = in_sizes[1] / 2;        // 3200000 (elements/2 regardless of int width)
    if (n > MAXN) n = MAXN;
    if (e > MAXE) e = MAXE;
    int ntiles = (n + SCAN_TILE - 1) / SCAN_TILE;

    // 1: zero+sniff || node1
    int nbz = (n + 127) / 128;
    k_init_node1<<<nbz + nbz, 128>>>((const int*)ei, x, W1, a1d, n, nbz);

    // 2: histogram + ranks
    k_hist<<<(e + 255) / 256, 256>>>(ei, e, n);

    // 3: single-pass scan + scatter
    int nbsc = (e + 1023) / 1024;
    k_scan_scatter<<<ntiles + nbsc, 256>>>(ei, e, n, ntiles);

    // 4: layer-1 edge aggregation + fused layer-2 node transform
    long long threads = (long long)n * GRP;
    unsigned blocks = (unsigned)((threads + 255) / 256);
    k_edge<1><<<blocks, 256>>>(b1, a1s, W2, a2d, nullptr, n);

    // 5: layer-2 edge aggregation -> final output
    k_edge<0><<<blocks, 256>>>(b2, a2s, nullptr, nullptr, out, n);
}